// round 13
// baseline (speedup 1.0000x reference)
#include <cuda_runtime.h>
#include <cuda_fp16.h>
#include <cstdint>
#include <math.h>

#define B_  4
#define T_  1024
#define E_  1024
#define H_  16
#define HS_ 64
#define D_  1024
#define V_  32000
#define BT_ 4096
#define QKV3 (3*D_)
#define PN_  (V_/32)        // LSE partials per row

// ---------------- scratch (device globals; no allocation allowed) ----------
__device__ __half g_hh[BT_*E_];                         // embed fp16
__device__ float  g_qkv[BT_*QKV3];                      // q|k|v fp32
__device__ __half g_oh[BT_*D_];                         // attn out fp16
__device__ __half g_fh[BT_*D_];                         // ff out fp16
__device__ __half g_wqkvh[(size_t)E_*QKV3];             // [k][n]
__device__ __half g_wfh[(size_t)D_*D_];                 // [k][n]
__device__ __half g_wch[(size_t)D_*V_];                 // [k][n]
__device__ float  g_pm[(size_t)BT_*PN_], g_ps[(size_t)BT_*PN_];
__device__ float  g_loss[BT_];

// ---------------- FFMA-only exp2 / exp --------------------------------------
__device__ __forceinline__ float fast_exp2(float y) {
    y = fmaxf(y, -126.0f);
    float r = y + 12582912.0f;               // round-to-nearest-int trick
    int   n = __float_as_int(r) - 0x4B400000;
    float f = y - (r - 12582912.0f);         // frac in [-0.5, 0.5]
    float p =             1.33335581e-3f;
    p = fmaf(p, f, 9.61812911e-3f);
    p = fmaf(p, f, 5.55041087e-2f);
    p = fmaf(p, f, 2.40226507e-1f);
    p = fmaf(p, f, 6.93147181e-1f);
    p = fmaf(p, f, 1.0f);
    return p * __int_as_float((n + 127) << 23);
}
__device__ __forceinline__ float fast_exp(float x) {
    return fast_exp2(x * 1.44269504f);
}

// ---------------- embedding: h = tok_emb[x] + pos_emb[t] -> fp16 ------------
__global__ __launch_bounds__(256) void embed_split(const int* __restrict__ x,
                                                   const float* __restrict__ tok,
                                                   const float* __restrict__ pos) {
    int idx = blockIdx.x * 256 + threadIdx.x;
    int r = idx >> 8;
    int c = idx & 255;
    int token = x[r];
    int t = r & (T_ - 1);
    float4 a = ((const float4*)tok)[(size_t)token * 256 + c];
    float4 b = ((const float4*)pos)[(size_t)t * 256 + c];
    ((__half2*)g_hh)[idx * 2 + 0] = __halves2half2(
        __float2half(a.x + b.x), __float2half(a.y + b.y));
    ((__half2*)g_hh)[idx * 2 + 1] = __halves2half2(
        __float2half(a.z + b.z), __float2half(a.w + b.w));
}

// ---------------- elementwise fp32 -> fp16 convert ---------------------------
__global__ __launch_bounds__(256) void wconv(const float* __restrict__ W,
                                             __half* __restrict__ hi) {
    size_t i = ((size_t)blockIdx.x * 256 + threadIdx.x) * 4;
    float4 v = *(const float4*)(W + i);
    ((__half2*)(hi + i))[0] = __halves2half2(__float2half(v.x), __float2half(v.y));
    ((__half2*)(hi + i))[1] = __halves2half2(__float2half(v.z), __float2half(v.w));
}

// QKV gather convert: W[H][E][HS] fp32 -> out[k][h*64+hs] fp16 (stride QKV3)
__global__ __launch_bounds__(256) void wconv_qkv(const float* __restrict__ W,
                                                 __half* __restrict__ out) {
    int idx = blockIdx.x * 256 + threadIdx.x;
    int i = idx << 2;
    int h  = i >> 16;
    int k  = (i >> 6) & 1023;
    int hs = i & 63;
    float4 v = ((const float4*)W)[idx];
    size_t o = (size_t)k * QKV3 + h * 64 + hs;
    ((__half2*)(out + o))[0] = __halves2half2(__float2half(v.x), __float2half(v.y));
    ((__half2*)(out + o))[1] = __halves2half2(__float2half(v.z), __float2half(v.w));
}

// ---------------- fp16 tensor-core GEMM (B in [K][N] layout) ----------------
// OUTMODE: 0 = fp32 C, 2 = half C
#define SSTR  40
#define ATILE (128*SSTR)
#define SSTRB 136
#define BTILE (32*SSTRB)

__device__ __forceinline__ void cpa16(uint32_t dst, const void* src) {
    asm volatile("cp.async.cg.shared.global [%0], [%1], 16;\n" :: "r"(dst), "l"(src));
}
#define LDM4(R, ADDR) \
    asm volatile("ldmatrix.sync.aligned.m8n8.x4.shared.b16 {%0,%1,%2,%3}, [%4];" \
        : "=r"(R[0]), "=r"(R[1]), "=r"(R[2]), "=r"(R[3]) : "r"(ADDR))
#define LDM4T(R, ADDR) \
    asm volatile("ldmatrix.sync.aligned.m8n8.x4.trans.shared.b16 {%0,%1,%2,%3}, [%4];" \
        : "=r"(R[0]), "=r"(R[1]), "=r"(R[2]), "=r"(R[3]) : "r"(ADDR))
#define MMAF16(Cc, Aa, B0, B1) \
    asm volatile("mma.sync.aligned.m16n8k16.row.col.f32.f16.f16.f32 " \
        "{%0,%1,%2,%3}, {%4,%5,%6,%7}, {%8,%9}, {%0,%1,%2,%3};" \
        : "+f"(Cc[0]), "+f"(Cc[1]), "+f"(Cc[2]), "+f"(Cc[3]) \
        : "r"(Aa[0]), "r"(Aa[1]), "r"(Aa[2]), "r"(Aa[3]), "r"(B0), "r"(B1))

template <int HASBIAS, int RELU, int OUTMODE, int LSE>
__global__ __launch_bounds__(256) void mma_gemm(
    const __half* __restrict__ Ah,
    const __half* __restrict__ Bh,
    const float* __restrict__ bias, float* __restrict__ C,
    __half* __restrict__ Ch,
    int M, int N, int K)
{
    extern __shared__ __half sm[];
    constexpr int STG = ATILE + BTILE;
    const int m0 = blockIdx.x * 128, n0 = blockIdx.y * 128;
    const int tid = threadIdx.x;
    const int lane = tid & 31, w = tid >> 5;
    const int wm = w >> 2, wn = w & 3;
    const uint32_t smb = (uint32_t)__cvta_generic_to_shared(sm);

    const int nk = K >> 5;

    auto load_stage = [&](int s, int k0g) {
#pragma unroll
        for (int hlf = 0; hlf < 2; hlf++) {
            int rem = (hlf << 8) + tid;
            int row = rem >> 2, seg = tid & 3;
            const __half* src = Ah + (size_t)(m0 + row) * K + k0g + seg * 8;
            uint32_t dst = smb + (uint32_t)((s * STG + row * SSTR + seg * 8) << 1);
            cpa16(dst, src);
        }
#pragma unroll
        for (int it = 0; it < 2; it++) {
            int idx = it * 256 + tid;
            int row = idx >> 4, seg = idx & 15;
            const __half* src = Bh + (size_t)(k0g + row) * N + n0 + seg * 8;
            uint32_t dst = smb + (uint32_t)((s * STG + ATILE + row * SSTRB + seg * 8) << 1);
            cpa16(dst, src);
        }
        asm volatile("cp.async.commit_group;\n" ::: "memory");
    };

    load_stage(0, 0);
    load_stage(1, 32);

    float acc[4][4][4];
#pragma unroll
    for (int a = 0; a < 4; a++)
#pragma unroll
        for (int b = 0; b < 4; b++)
#pragma unroll
            for (int c = 0; c < 4; c++) acc[a][b][c] = 0.f;

    const int t8 = lane >> 3, r8 = lane & 7;
    const int g2 = lane >> 3;

    for (int kt = 0; kt < nk; kt++) {
        asm volatile("cp.async.wait_group 1;\n" ::: "memory");
        __syncthreads();
        const uint32_t base = smb + (uint32_t)(((kt & 1) * STG) << 1);
#pragma unroll
        for (int kk = 0; kk < 2; kk++) {
            const int kof = kk << 4;
            uint32_t ah[4][4], bh[2][4];
#pragma unroll
            for (int mt = 0; mt < 4; mt++) {
                int mrow = wm * 64 + mt * 16 + ((t8 & 1) << 3) + r8;
                int kcol = kof + ((t8 >> 1) << 3);
                uint32_t ad = base + (uint32_t)((mrow * SSTR + kcol) << 1);
                LDM4(ah[mt], ad);
            }
#pragma unroll
            for (int np = 0; np < 2; np++) {
                int krow = kof + ((g2 & 1) << 3) + (lane & 7);
                int ncol = wn * 32 + np * 16 + ((g2 >> 1) << 3);
                uint32_t bd = base + (uint32_t)((ATILE + krow * SSTRB + ncol) << 1);
                LDM4T(bh[np], bd);
            }
#pragma unroll
            for (int mt = 0; mt < 4; mt++)
#pragma unroll
                for (int np = 0; np < 2; np++)
#pragma unroll
                    for (int hf = 0; hf < 2; hf++) {
                        float* cc = acc[mt][np * 2 + hf];
                        MMAF16(cc, ah[mt], bh[np][hf * 2], bh[np][hf * 2 + 1]);
                    }
        }
        __syncthreads();
        if (kt + 2 < nk) load_stage(kt & 1, (kt + 2) << 5);
        else asm volatile("cp.async.commit_group;\n" ::: "memory");
    }

    // ---------------- epilogue ----------------
    float bj[8];
#pragma unroll
    for (int nt = 0; nt < 4; nt++) {
        int col = n0 + wn * 32 + nt * 8 + ((lane & 3) << 1);
        bj[nt * 2 + 0] = HASBIAS ? bias[col] : 0.f;
        bj[nt * 2 + 1] = HASBIAS ? bias[col + 1] : 0.f;
    }
#pragma unroll
    for (int mt = 0; mt < 4; mt++) {
#pragma unroll
        for (int hf = 0; hf < 2; hf++) {
            int row = m0 + wm * 64 + mt * 16 + (lane >> 2) + hf * 8;
            float vv[8];
            float vmax = -INFINITY;
#pragma unroll
            for (int nt = 0; nt < 4; nt++) {
#pragma unroll
                for (int j = 0; j < 2; j++) {
                    float v = acc[mt][nt][hf * 2 + j] + bj[nt * 2 + j];
                    if (RELU) v = fmaxf(v, 0.f);
                    vv[nt * 2 + j] = v;
                    vmax = fmaxf(vmax, v);
                }
            }
#pragma unroll
            for (int nt = 0; nt < 4; nt++) {
                int col = n0 + wn * 32 + nt * 8 + ((lane & 3) << 1);
                if (OUTMODE == 2) {
                    *(__half2*)(Ch + (size_t)row * N + col) = __halves2half2(
                        __float2half(vv[nt * 2]), __float2half(vv[nt * 2 + 1]));
                } else {
                    float2 o; o.x = vv[nt * 2]; o.y = vv[nt * 2 + 1];
                    *(float2*)(C + (size_t)row * N + col) = o;
                }
            }
            if (LSE) {
                float rs = 0.f;
#pragma unroll
                for (int k = 0; k < 8; k++) rs += fast_exp(vv[k] - vmax);
                float rm = vmax;
#pragma unroll
                for (int off = 1; off <= 2; off <<= 1) {
                    float m2 = __shfl_xor_sync(0xFFFFFFFFu, rm, off);
                    float s2 = __shfl_xor_sync(0xFFFFFFFFu, rs, off);
                    float mn = fmaxf(rm, m2);
                    rs = rs * fast_exp(rm - mn) + s2 * fast_exp(m2 - mn);
                    rm = mn;
                }
                if ((lane & 3) == 0) {
                    int pcol = blockIdx.y * 4 + wn;
                    g_pm[(size_t)row * PN_ + pcol] = rm;
                    g_ps[(size_t)row * PN_ + pcol] = rs;
                }
            }
        }
    }
}

// ---------------- causal attention (fp32, log2-domain online softmax) -------
// work-balanced tile pairs; exps computed in a dedicated FFMA loop (no MUFU)
__global__ __launch_bounds__(128) void attn_kernel() {
    __shared__ float kv[64][64];
    __shared__ float sc[64][128];
    const int z   = blockIdx.y;
    const int b   = z >> 4;
    const int hh  = z & 15;
    const int tid = threadIdx.x;
    const int ntiles = T_ / 128;               // 8

#pragma unroll
    for (int half = 0; half < 2; half++) {
        const int bx = half == 0 ? (ntiles - 1 - blockIdx.x) : blockIdx.x;
        const int t  = bx * 128 + tid;

        const float4* qp = (const float4*)(g_qkv + (size_t)(b * T_ + t) * QKV3 + hh * HS_);
        float q[64];
#pragma unroll
        for (int d4 = 0; d4 < 16; d4++) {
            float4 qq = qp[d4];
            const float qs = 8.0f * 1.44269504f;   // sqrt(HS) * log2(e)
            q[d4 * 4 + 0] = qq.x * qs;
            q[d4 * 4 + 1] = qq.y * qs;
            q[d4 * 4 + 2] = qq.z * qs;
            q[d4 * 4 + 3] = qq.w * qs;
        }

        float acc[64];
#pragma unroll
        for (int d = 0; d < 64; d++) acc[d] = 0.f;
        float m = -INFINITY, l = 0.f;          // m in log2 domain

        const int smax = bx * 128 + 127;
        for (int s0 = 0; s0 <= smax; s0 += 64) {
            const float* kbase = g_qkv + (size_t)(b * T_ + s0) * QKV3 + D_ + hh * HS_;
#pragma unroll
            for (int i = 0; i < 8; i++) {
                int lin = tid + 128 * i;
                int row = lin >> 4, c4 = lin & 15;
                *(float4*)&kv[row][c4 * 4] =
                    *(const float4*)(kbase + (size_t)row * QKV3 + c4 * 4);
            }
            __syncthreads();

            int cnt = t - s0 + 1;
            cnt = cnt < 0 ? 0 : (cnt > 64 ? 64 : cnt);
            for (int j = 0; j < cnt; j++) {
                const float4* kr = (const float4*)kv[j];
                float s = 0.f;
#pragma unroll
                for (int d4 = 0; d4 < 16; d4++) {
                    float4 kk = kr[d4];
                    s = fmaf(q[d4 * 4 + 0], kk.x, s);
                    s = fmaf(q[d4 * 4 + 1], kk.y, s);
                    s = fmaf(q[d4 * 4 + 2], kk.z, s);
                    s = fmaf(q[d4 * 4 + 3], kk.w, s);
                }
                sc[j][tid] = s;
            }
            __syncthreads();

            const float* vbase = g_qkv + (size_t)(b * T_ + s0) * QKV3 + 2 * D_ + hh * HS_;
#pragma unroll
            for (int i = 0; i < 8; i++) {
                int lin = tid + 128 * i;
                int row = lin >> 4, c4 = lin & 15;
                *(float4*)&kv[row][c4 * 4] =
                    *(const float4*)(vbase + (size_t)row * QKV3 + c4 * 4);
            }
            __syncthreads();

            if (cnt > 0) {
                // phase 1: max (log2 domain)
                float tmax = -INFINITY;
                for (int j = 0; j < cnt; j++) tmax = fmaxf(tmax, sc[j][tid]);
                float mn = fmaxf(m, tmax);
                float scale = fast_exp2(m - mn);
                l *= scale;
#pragma unroll
                for (int d = 0; d < 64; d++) acc[d] *= scale;
                // phase 2: exps in a dedicated low-pressure loop (FFMA only)
                float lsum = 0.f;
                for (int j = 0; j < cnt; j++) {
                    float p = fast_exp2(sc[j][tid] - mn);
                    sc[j][tid] = p;
                    lsum += p;
                }
                l += lsum;
                // phase 3: PV accumulation, pure FMA
                for (int j = 0; j < cnt; j++) {
                    float p = sc[j][tid];
                    const float4* vr = (const float4*)kv[j];
#pragma unroll
                    for (int d4 = 0; d4 < 16; d4++) {
                        float4 vv4 = vr[d4];
                        acc[d4 * 4 + 0] = fmaf(p, vv4.x, acc[d4 * 4 + 0]);
                        acc[d4 * 4 + 1] = fmaf(p, vv4.y, acc[d4 * 4 + 1]);
                        acc[d4 * 4 + 2] = fmaf(p, vv4.z, acc[d4 * 4 + 2]);
                        acc[d4 * 4 + 3] = fmaf(p, vv4.w, acc[d4 * 4 + 3]);
                    }
                }
                m = mn;
            }
            __syncthreads();
        }

        float inv = 1.f / l;
        size_t obase = (size_t)(b * T_ + t) * D_ + hh * HS_;
#pragma unroll
        for (int d = 0; d < 64; d += 2) {
            float v0 = acc[d] * inv, v1 = acc[d + 1] * inv;
            *(__half2*)(g_oh + obase + d) =
                __halves2half2(__float2half(v0), __float2half(v1));
        }
        __syncthreads();
    }
}

// ---------------- loss from LSE partials -------------------------------------
__global__ __launch_bounds__(256) void loss_partial_kernel(const float* __restrict__ logits,
                                                           const int* __restrict__ y) {
    __shared__ float sm_m[256], sm_s[256];
    int row = blockIdx.x;
    int tid = threadIdx.x;
    float m = -INFINITY, s = 0.f;
    for (int i = tid; i < PN_; i += 256) {
        float m2 = g_pm[(size_t)row * PN_ + i];
        float s2 = g_ps[(size_t)row * PN_ + i];
        float mn = fmaxf(m, m2);
        s = s * fast_exp(m - mn) + s2 * fast_exp(m2 - mn);
        m = mn;
    }
    sm_m[tid] = m; sm_s[tid] = s;
    __syncthreads();
    for (int k = 128; k > 0; k >>= 1) {
        if (tid < k) {
            float m2 = sm_m[tid + k], s2 = sm_s[tid + k];
            float mn = fmaxf(sm_m[tid], m2);
            sm_s[tid] = sm_s[tid] * fast_exp(sm_m[tid] - mn) + s2 * fast_exp(m2 - mn);
            sm_m[tid] = mn;
        }
        __syncthreads();
    }
    if (tid == 0) {
        g_loss[row] = sm_m[0] + logf(sm_s[0]) - logits[(size_t)row * V_ + y[row]];
    }
}

__global__ __launch_bounds__(256) void loss_mean_kernel(float* out) {
    __shared__ float red[256];
    int tid = threadIdx.x;
    float s = 0.f;
    for (int i = tid; i < BT_; i += 256) s += g_loss[i];
    red[tid] = s;
    __syncthreads();
    for (int k = 128; k > 0; k >>= 1) {
        if (tid < k) red[tid] += red[tid + k];
        __syncthreads();
    }
    if (tid == 0) *out = red[0] / (float)BT_;
}

// ---------------- launch ----------------------------------------------------
extern "C" void kernel_launch(void* const* d_in, const int* in_sizes, int n_in,
                              void* d_out, int out_size) {
    const int*   x   = (const int*)d_in[0];
    const int*   y   = (const int*)d_in[1];
    const float* tok = (const float*)d_in[2];
    const float* pos = (const float*)d_in[3];
    const float* Wq  = (const float*)d_in[4];
    const float* Wk  = (const float*)d_in[5];
    const float* Wv  = (const float*)d_in[6];
    const float* ffw = (const float*)d_in[7];
    const float* ffb = (const float*)d_in[8];
    const float* fcw = (const float*)d_in[9];
    const float* fcb = (const float*)d_in[10];
    float* out = (float*)d_out;

    __half *phh, *poh, *pfh, *pwqh, *pwfh, *pwch;
    float *pqkv;
    cudaGetSymbolAddress((void**)&phh, g_hh);
    cudaGetSymbolAddress((void**)&poh, g_oh);
    cudaGetSymbolAddress((void**)&pfh, g_fh);
    cudaGetSymbolAddress((void**)&pwqh, g_wqkvh);
    cudaGetSymbolAddress((void**)&pwfh, g_wfh);
    cudaGetSymbolAddress((void**)&pwch, g_wch);
    cudaGetSymbolAddress((void**)&pqkv, g_qkv);

    const int smem1 = 2 * (ATILE + BTILE) * 2;   // 37888 B
    cudaFuncSetAttribute(mma_gemm<0,0,0,0>, cudaFuncAttributeMaxDynamicSharedMemorySize, smem1);
    cudaFuncSetAttribute(mma_gemm<1,1,2,0>, cudaFuncAttributeMaxDynamicSharedMemorySize, smem1);
    cudaFuncSetAttribute(mma_gemm<1,0,0,1>, cudaFuncAttributeMaxDynamicSharedMemorySize, smem1);

    // embedding
    embed_split<<<(BT_ * E_ / 4) / 256, 256>>>(x, tok, pos);

    // weight converts (elementwise, no transpose)
    wconv_qkv<<<(H_*E_*HS_/4)/256, 256>>>(Wq, pwqh);
    wconv_qkv<<<(H_*E_*HS_/4)/256, 256>>>(Wk, pwqh + D_);
    wconv_qkv<<<(H_*E_*HS_/4)/256, 256>>>(Wv, pwqh + 2*D_);
    wconv<<<(D_*D_/4)/256, 256>>>(ffw, pwfh);
    wconv<<<((size_t)D_*V_/4)/256, 256>>>(fcw, pwch);

    // fused QKV GEMM: [4096,3072] = h @ Wqkv[k][n]  (1-pass fp16)
    mma_gemm<0,0,0,0><<<dim3(BT_/128, QKV3/128), 256, smem1>>>(
        phh, pwqh, nullptr, pqkv, nullptr, BT_, QKV3, E_);

    // attention (work-balanced tile pairs, MUFU-free softmax)
    attn_kernel<<<dim3(T_/256, B_*H_), 128>>>();

    // FF: relu(o @ ff_w + ff_b) -> fp16 (1-pass)
    mma_gemm<1,1,2,0><<<dim3(BT_/128, D_/128), 256, smem1>>>(
        poh, pwfh, ffb, nullptr, pfh, BT_, D_, D_);

    // logits: ff @ fc_w + fc_b -> d_out fp32 (1-pass, fused LSE partials)
    mma_gemm<1,0,0,1><<<dim3(BT_/128, V_/128), 256, smem1>>>(
        pfh, pwch, fcb, out, nullptr, BT_, V_, D_);

    // loss
    loss_partial_kernel<<<BT_, 256>>>(out, y);
    long long logits_elems = (long long)BT_ * V_;
    if ((long long)out_size > logits_elems) {
        loss_mean_kernel<<<1, 256>>>(out + (size_t)logits_elems);
    }
}

// round 14
// speedup vs baseline: 1.1874x; 1.1874x over previous
#include <cuda_runtime.h>
#include <cuda_fp16.h>
#include <cstdint>
#include <math.h>

#define B_  4
#define T_  1024
#define E_  1024
#define H_  16
#define HS_ 64
#define D_  1024
#define V_  32000
#define BT_ 4096
#define QKV3 (3*D_)
#define PN_  (V_/32)        // LSE partials per row

// ---------------- scratch (device globals; no allocation allowed) ----------
__device__ __half g_hh[BT_*E_];                         // embed fp16
__device__ float  g_qkv[BT_*QKV3];                      // q|k|v fp32
__device__ __half g_oh[BT_*D_];                         // attn out fp16
__device__ __half g_fh[BT_*D_];                         // ff out fp16
__device__ __half g_wqkvh[(size_t)E_*QKV3];             // [k][n]
__device__ __half g_wfh[(size_t)D_*D_];                 // [k][n]
__device__ __half g_wch[(size_t)D_*V_];                 // [k][n]
__device__ float  g_pm[(size_t)BT_*PN_], g_ps[(size_t)BT_*PN_];
__device__ float  g_loss[BT_];

// ---------------- packed f32x2 helpers (Blackwell) ---------------------------
#define FMA_X2(d, a, b, c) \
    asm("fma.rn.f32x2 %0, %1, %2, %3;" : "=l"(d) : "l"(a), "l"(b), "l"(c))
#define MUL_X2(d, a, b) \
    asm("mul.rn.f32x2 %0, %1, %2;" : "=l"(d) : "l"(a), "l"(b))
__device__ __forceinline__ uint64_t pack2(float lo, float hi) {
    uint64_t r;
    asm("mov.b64 %0, {%1, %2};" : "=l"(r) : "f"(lo), "f"(hi));
    return r;
}
__device__ __forceinline__ void unpack2(uint64_t v, float& lo, float& hi) {
    asm("mov.b64 {%0, %1}, %2;" : "=f"(lo), "=f"(hi) : "l"(v));
}

// ---------------- FFMA-only exp (low-register contexts) ---------------------
__device__ __forceinline__ float fast_exp(float x) {
    float y = fmaxf(x * 1.44269504f, -126.0f);
    float r = y + 12582912.0f;
    int   n = __float_as_int(r) - 0x4B400000;
    float f = y - (r - 12582912.0f);
    float p =             1.33335581e-3f;
    p = fmaf(p, f, 9.61812911e-3f);
    p = fmaf(p, f, 5.55041087e-2f);
    p = fmaf(p, f, 2.40226507e-1f);
    p = fmaf(p, f, 6.93147181e-1f);
    p = fmaf(p, f, 1.0f);
    return p * __int_as_float((n + 127) << 23);
}

// ---------------- embedding: h = tok_emb[x] + pos_emb[t] -> fp16 ------------
__global__ __launch_bounds__(256) void embed_split(const int* __restrict__ x,
                                                   const float* __restrict__ tok,
                                                   const float* __restrict__ pos) {
    int idx = blockIdx.x * 256 + threadIdx.x;
    int r = idx >> 8;
    int c = idx & 255;
    int token = x[r];
    int t = r & (T_ - 1);
    float4 a = ((const float4*)tok)[(size_t)token * 256 + c];
    float4 b = ((const float4*)pos)[(size_t)t * 256 + c];
    ((__half2*)g_hh)[idx * 2 + 0] = __halves2half2(
        __float2half(a.x + b.x), __float2half(a.y + b.y));
    ((__half2*)g_hh)[idx * 2 + 1] = __halves2half2(
        __float2half(a.z + b.z), __float2half(a.w + b.w));
}

// ---------------- elementwise fp32 -> fp16 convert ---------------------------
__global__ __launch_bounds__(256) void wconv(const float* __restrict__ W,
                                             __half* __restrict__ hi) {
    size_t i = ((size_t)blockIdx.x * 256 + threadIdx.x) * 4;
    float4 v = *(const float4*)(W + i);
    ((__half2*)(hi + i))[0] = __halves2half2(__float2half(v.x), __float2half(v.y));
    ((__half2*)(hi + i))[1] = __halves2half2(__float2half(v.z), __float2half(v.w));
}

// QKV gather convert: W[H][E][HS] fp32 -> out[k][h*64+hs] fp16 (stride QKV3)
__global__ __launch_bounds__(256) void wconv_qkv(const float* __restrict__ W,
                                                 __half* __restrict__ out) {
    int idx = blockIdx.x * 256 + threadIdx.x;
    int i = idx << 2;
    int h  = i >> 16;
    int k  = (i >> 6) & 1023;
    int hs = i & 63;
    float4 v = ((const float4*)W)[idx];
    size_t o = (size_t)k * QKV3 + h * 64 + hs;
    ((__half2*)(out + o))[0] = __halves2half2(__float2half(v.x), __float2half(v.y));
    ((__half2*)(out + o))[1] = __halves2half2(__float2half(v.z), __float2half(v.w));
}

// ---------------- fp16 tensor-core GEMM (B in [K][N] layout) ----------------
// OUTMODE: 0 = fp32 C, 2 = half C
#define SSTR  40
#define ATILE (128*SSTR)
#define SSTRB 136
#define BTILE (32*SSTRB)

__device__ __forceinline__ void cpa16(uint32_t dst, const void* src) {
    asm volatile("cp.async.cg.shared.global [%0], [%1], 16;\n" :: "r"(dst), "l"(src));
}
#define LDM4(R, ADDR) \
    asm volatile("ldmatrix.sync.aligned.m8n8.x4.shared.b16 {%0,%1,%2,%3}, [%4];" \
        : "=r"(R[0]), "=r"(R[1]), "=r"(R[2]), "=r"(R[3]) : "r"(ADDR))
#define LDM4T(R, ADDR) \
    asm volatile("ldmatrix.sync.aligned.m8n8.x4.trans.shared.b16 {%0,%1,%2,%3}, [%4];" \
        : "=r"(R[0]), "=r"(R[1]), "=r"(R[2]), "=r"(R[3]) : "r"(ADDR))
#define MMAF16(Cc, Aa, B0, B1) \
    asm volatile("mma.sync.aligned.m16n8k16.row.col.f32.f16.f16.f32 " \
        "{%0,%1,%2,%3}, {%4,%5,%6,%7}, {%8,%9}, {%0,%1,%2,%3};" \
        : "+f"(Cc[0]), "+f"(Cc[1]), "+f"(Cc[2]), "+f"(Cc[3]) \
        : "r"(Aa[0]), "r"(Aa[1]), "r"(Aa[2]), "r"(Aa[3]), "r"(B0), "r"(B1))

template <int HASBIAS, int RELU, int OUTMODE, int LSE>
__global__ __launch_bounds__(256) void mma_gemm(
    const __half* __restrict__ Ah,
    const __half* __restrict__ Bh,
    const float* __restrict__ bias, float* __restrict__ C,
    __half* __restrict__ Ch,
    int M, int N, int K)
{
    extern __shared__ __half sm[];
    constexpr int STG = ATILE + BTILE;
    const int m0 = blockIdx.x * 128, n0 = blockIdx.y * 128;
    const int tid = threadIdx.x;
    const int lane = tid & 31, w = tid >> 5;
    const int wm = w >> 2, wn = w & 3;
    const uint32_t smb = (uint32_t)__cvta_generic_to_shared(sm);

    const int nk = K >> 5;

    auto load_stage = [&](int s, int k0g) {
#pragma unroll
        for (int hlf = 0; hlf < 2; hlf++) {
            int rem = (hlf << 8) + tid;
            int row = rem >> 2, seg = tid & 3;
            const __half* src = Ah + (size_t)(m0 + row) * K + k0g + seg * 8;
            uint32_t dst = smb + (uint32_t)((s * STG + row * SSTR + seg * 8) << 1);
            cpa16(dst, src);
        }
#pragma unroll
        for (int it = 0; it < 2; it++) {
            int idx = it * 256 + tid;
            int row = idx >> 4, seg = idx & 15;
            const __half* src = Bh + (size_t)(k0g + row) * N + n0 + seg * 8;
            uint32_t dst = smb + (uint32_t)((s * STG + ATILE + row * SSTRB + seg * 8) << 1);
            cpa16(dst, src);
        }
        asm volatile("cp.async.commit_group;\n" ::: "memory");
    };

    load_stage(0, 0);
    load_stage(1, 32);

    float acc[4][4][4];
#pragma unroll
    for (int a = 0; a < 4; a++)
#pragma unroll
        for (int b = 0; b < 4; b++)
#pragma unroll
            for (int c = 0; c < 4; c++) acc[a][b][c] = 0.f;

    const int t8 = lane >> 3, r8 = lane & 7;
    const int g2 = lane >> 3;

    for (int kt = 0; kt < nk; kt++) {
        asm volatile("cp.async.wait_group 1;\n" ::: "memory");
        __syncthreads();
        const uint32_t base = smb + (uint32_t)(((kt & 1) * STG) << 1);
#pragma unroll
        for (int kk = 0; kk < 2; kk++) {
            const int kof = kk << 4;
            uint32_t ah[4][4], bh[2][4];
#pragma unroll
            for (int mt = 0; mt < 4; mt++) {
                int mrow = wm * 64 + mt * 16 + ((t8 & 1) << 3) + r8;
                int kcol = kof + ((t8 >> 1) << 3);
                uint32_t ad = base + (uint32_t)((mrow * SSTR + kcol) << 1);
                LDM4(ah[mt], ad);
            }
#pragma unroll
            for (int np = 0; np < 2; np++) {
                int krow = kof + ((g2 & 1) << 3) + (lane & 7);
                int ncol = wn * 32 + np * 16 + ((g2 >> 1) << 3);
                uint32_t bd = base + (uint32_t)((ATILE + krow * SSTRB + ncol) << 1);
                LDM4T(bh[np], bd);
            }
#pragma unroll
            for (int mt = 0; mt < 4; mt++)
#pragma unroll
                for (int np = 0; np < 2; np++)
#pragma unroll
                    for (int hf = 0; hf < 2; hf++) {
                        float* cc = acc[mt][np * 2 + hf];
                        MMAF16(cc, ah[mt], bh[np][hf * 2], bh[np][hf * 2 + 1]);
                    }
        }
        __syncthreads();
        if (kt + 2 < nk) load_stage(kt & 1, (kt + 2) << 5);
        else asm volatile("cp.async.commit_group;\n" ::: "memory");
    }

    // ---------------- epilogue ----------------
    float bj[8];
#pragma unroll
    for (int nt = 0; nt < 4; nt++) {
        int col = n0 + wn * 32 + nt * 8 + ((lane & 3) << 1);
        bj[nt * 2 + 0] = HASBIAS ? bias[col] : 0.f;
        bj[nt * 2 + 1] = HASBIAS ? bias[col + 1] : 0.f;
    }
#pragma unroll
    for (int mt = 0; mt < 4; mt++) {
#pragma unroll
        for (int hf = 0; hf < 2; hf++) {
            int row = m0 + wm * 64 + mt * 16 + (lane >> 2) + hf * 8;
            float vv[8];
            float vmax = -INFINITY;
#pragma unroll
            for (int nt = 0; nt < 4; nt++) {
#pragma unroll
                for (int j = 0; j < 2; j++) {
                    float v = acc[mt][nt][hf * 2 + j] + bj[nt * 2 + j];
                    if (RELU) v = fmaxf(v, 0.f);
                    vv[nt * 2 + j] = v;
                    vmax = fmaxf(vmax, v);
                }
            }
#pragma unroll
            for (int nt = 0; nt < 4; nt++) {
                int col = n0 + wn * 32 + nt * 8 + ((lane & 3) << 1);
                if (OUTMODE == 2) {
                    *(__half2*)(Ch + (size_t)row * N + col) = __halves2half2(
                        __float2half(vv[nt * 2]), __float2half(vv[nt * 2 + 1]));
                } else {
                    float2 o; o.x = vv[nt * 2]; o.y = vv[nt * 2 + 1];
                    *(float2*)(C + (size_t)row * N + col) = o;
                }
            }
            if (LSE) {
                float rs = 0.f;
#pragma unroll
                for (int k = 0; k < 8; k++) rs += fast_exp(vv[k] - vmax);
                float rm = vmax;
#pragma unroll
                for (int off = 1; off <= 2; off <<= 1) {
                    float m2 = __shfl_xor_sync(0xFFFFFFFFu, rm, off);
                    float s2 = __shfl_xor_sync(0xFFFFFFFFu, rs, off);
                    float mn = fmaxf(rm, m2);
                    rs = rs * fast_exp(rm - mn) + s2 * fast_exp(m2 - mn);
                    rm = mn;
                }
                if ((lane & 3) == 0) {
                    int pcol = blockIdx.y * 4 + wn;
                    g_pm[(size_t)row * PN_ + pcol] = rm;
                    g_ps[(size_t)row * PN_ + pcol] = rs;
                }
            }
        }
    }
}

// ---------------- causal attention (packed f32x2 math, online softmax) ------
// work-balanced tile pairs (R12 structure); score/PV loops use fma.rn.f32x2
__global__ __launch_bounds__(128) void attn_kernel() {
    __shared__ float kv[64][64];
    __shared__ float sc[64][128];
    const int z   = blockIdx.y;
    const int b   = z >> 4;
    const int hh  = z & 15;
    const int tid = threadIdx.x;
    const int ntiles = T_ / 128;               // 8

#pragma unroll
    for (int half = 0; half < 2; half++) {
        const int bx = half == 0 ? (ntiles - 1 - blockIdx.x) : blockIdx.x;
        const int t  = bx * 128 + tid;

        const float4* qp = (const float4*)(g_qkv + (size_t)(b * T_ + t) * QKV3 + hh * HS_);
        uint64_t q2[32];
#pragma unroll
        for (int d4 = 0; d4 < 16; d4++) {
            float4 qq = qp[d4];
            q2[d4 * 2 + 0] = pack2(qq.x * 8.0f, qq.y * 8.0f);   // * sqrt(HS)
            q2[d4 * 2 + 1] = pack2(qq.z * 8.0f, qq.w * 8.0f);
        }

        uint64_t acc2[32];
#pragma unroll
        for (int d = 0; d < 32; d++) acc2[d] = 0ull;
        float m = -INFINITY, l = 0.f;

        const int smax = bx * 128 + 127;
        for (int s0 = 0; s0 <= smax; s0 += 64) {
            const float* kbase = g_qkv + (size_t)(b * T_ + s0) * QKV3 + D_ + hh * HS_;
#pragma unroll
            for (int i = 0; i < 8; i++) {
                int lin = tid + 128 * i;
                int row = lin >> 4, c4 = lin & 15;
                *(float4*)&kv[row][c4 * 4] =
                    *(const float4*)(kbase + (size_t)row * QKV3 + c4 * 4);
            }
            __syncthreads();

            int cnt = t - s0 + 1;
            cnt = cnt < 0 ? 0 : (cnt > 64 ? 64 : cnt);
            for (int j = 0; j < cnt; j++) {
                const uint64_t* kr = (const uint64_t*)kv[j];
                uint64_t s2 = 0ull;
#pragma unroll
                for (int d2 = 0; d2 < 32; d2++) {
                    FMA_X2(s2, q2[d2], kr[d2], s2);
                }
                float lo, hi;
                unpack2(s2, lo, hi);
                sc[j][tid] = lo + hi;
            }
            __syncthreads();

            const float* vbase = g_qkv + (size_t)(b * T_ + s0) * QKV3 + 2 * D_ + hh * HS_;
#pragma unroll
            for (int i = 0; i < 8; i++) {
                int lin = tid + 128 * i;
                int row = lin >> 4, c4 = lin & 15;
                *(float4*)&kv[row][c4 * 4] =
                    *(const float4*)(vbase + (size_t)row * QKV3 + c4 * 4);
            }
            __syncthreads();

            if (cnt > 0) {
                float tmax = -INFINITY;
                for (int j = 0; j < cnt; j++) tmax = fmaxf(tmax, sc[j][tid]);
                float mn = fmaxf(m, tmax);
                float scale = __expf(m - mn);
                l *= scale;
                uint64_t sc2 = pack2(scale, scale);
#pragma unroll
                for (int d = 0; d < 32; d++) MUL_X2(acc2[d], acc2[d], sc2);
                for (int j = 0; j < cnt; j++) {
                    float p = __expf(sc[j][tid] - mn);
                    l += p;
                    uint64_t pp = pack2(p, p);
                    const uint64_t* vr = (const uint64_t*)kv[j];
#pragma unroll
                    for (int d2 = 0; d2 < 32; d2++) {
                        FMA_X2(acc2[d2], pp, vr[d2], acc2[d2]);
                    }
                }
                m = mn;
            }
            __syncthreads();
        }

        float inv = 1.f / l;
        size_t obase = (size_t)(b * T_ + t) * D_ + hh * HS_;
#pragma unroll
        for (int d2 = 0; d2 < 32; d2++) {
            float v0, v1;
            unpack2(acc2[d2], v0, v1);
            *(__half2*)(g_oh + obase + d2 * 2) =
                __halves2half2(__float2half(v0 * inv), __float2half(v1 * inv));
        }
        __syncthreads();
    }
}

// ---------------- loss from LSE partials -------------------------------------
__global__ __launch_bounds__(256) void loss_partial_kernel(const float* __restrict__ logits,
                                                           const int* __restrict__ y) {
    __shared__ float sm_m[256], sm_s[256];
    int row = blockIdx.x;
    int tid = threadIdx.x;
    float m = -INFINITY, s = 0.f;
    for (int i = tid; i < PN_; i += 256) {
        float m2 = g_pm[(size_t)row * PN_ + i];
        float s2 = g_ps[(size_t)row * PN_ + i];
        float mn = fmaxf(m, m2);
        s = s * fast_exp(m - mn) + s2 * fast_exp(m2 - mn);
        m = mn;
    }
    sm_m[tid] = m; sm_s[tid] = s;
    __syncthreads();
    for (int k = 128; k > 0; k >>= 1) {
        if (tid < k) {
            float m2 = sm_m[tid + k], s2 = sm_s[tid + k];
            float mn = fmaxf(sm_m[tid], m2);
            sm_s[tid] = sm_s[tid] * fast_exp(sm_m[tid] - mn) + s2 * fast_exp(m2 - mn);
            sm_m[tid] = mn;
        }
        __syncthreads();
    }
    if (tid == 0) {
        g_loss[row] = sm_m[0] + logf(sm_s[0]) - logits[(size_t)row * V_ + y[row]];
    }
}

__global__ __launch_bounds__(256) void loss_mean_kernel(float* out) {
    __shared__ float red[256];
    int tid = threadIdx.x;
    float s = 0.f;
    for (int i = tid; i < BT_; i += 256) s += g_loss[i];
    red[tid] = s;
    __syncthreads();
    for (int k = 128; k > 0; k >>= 1) {
        if (tid < k) red[tid] += red[tid + k];
        __syncthreads();
    }
    if (tid == 0) *out = red[0] / (float)BT_;
}

// ---------------- launch ----------------------------------------------------
extern "C" void kernel_launch(void* const* d_in, const int* in_sizes, int n_in,
                              void* d_out, int out_size) {
    const int*   x   = (const int*)d_in[0];
    const int*   y   = (const int*)d_in[1];
    const float* tok = (const float*)d_in[2];
    const float* pos = (const float*)d_in[3];
    const float* Wq  = (const float*)d_in[4];
    const float* Wk  = (const float*)d_in[5];
    const float* Wv  = (const float*)d_in[6];
    const float* ffw = (const float*)d_in[7];
    const float* ffb = (const float*)d_in[8];
    const float* fcw = (const float*)d_in[9];
    const float* fcb = (const float*)d_in[10];
    float* out = (float*)d_out;

    __half *phh, *poh, *pfh, *pwqh, *pwfh, *pwch;
    float *pqkv;
    cudaGetSymbolAddress((void**)&phh, g_hh);
    cudaGetSymbolAddress((void**)&poh, g_oh);
    cudaGetSymbolAddress((void**)&pfh, g_fh);
    cudaGetSymbolAddress((void**)&pwqh, g_wqkvh);
    cudaGetSymbolAddress((void**)&pwfh, g_wfh);
    cudaGetSymbolAddress((void**)&pwch, g_wch);
    cudaGetSymbolAddress((void**)&pqkv, g_qkv);

    const int smem1 = 2 * (ATILE + BTILE) * 2;   // 37888 B
    cudaFuncSetAttribute(mma_gemm<0,0,0,0>, cudaFuncAttributeMaxDynamicSharedMemorySize, smem1);
    cudaFuncSetAttribute(mma_gemm<1,1,2,0>, cudaFuncAttributeMaxDynamicSharedMemorySize, smem1);
    cudaFuncSetAttribute(mma_gemm<1,0,0,1>, cudaFuncAttributeMaxDynamicSharedMemorySize, smem1);

    // embedding
    embed_split<<<(BT_ * E_ / 4) / 256, 256>>>(x, tok, pos);

    // weight converts (elementwise, no transpose)
    wconv_qkv<<<(H_*E_*HS_/4)/256, 256>>>(Wq, pwqh);
    wconv_qkv<<<(H_*E_*HS_/4)/256, 256>>>(Wk, pwqh + D_);
    wconv_qkv<<<(H_*E_*HS_/4)/256, 256>>>(Wv, pwqh + 2*D_);
    wconv<<<(D_*D_/4)/256, 256>>>(ffw, pwfh);
    wconv<<<((size_t)D_*V_/4)/256, 256>>>(fcw, pwch);

    // fused QKV GEMM: [4096,3072] = h @ Wqkv[k][n]  (1-pass fp16)
    mma_gemm<0,0,0,0><<<dim3(BT_/128, QKV3/128), 256, smem1>>>(
        phh, pwqh, nullptr, pqkv, nullptr, BT_, QKV3, E_);

    // attention (work-balanced tile pairs, packed f32x2 math)
    attn_kernel<<<dim3(T_/256, B_*H_), 128>>>();

    // FF: relu(o @ ff_w + ff_b) -> fp16 (1-pass)
    mma_gemm<1,1,2,0><<<dim3(BT_/128, D_/128), 256, smem1>>>(
        poh, pwfh, ffb, nullptr, pfh, BT_, D_, D_);

    // logits: ff @ fc_w + fc_b -> d_out fp32 (1-pass, fused LSE partials)
    mma_gemm<1,0,0,1><<<dim3(BT_/128, V_/128), 256, smem1>>>(
        pfh, pwch, fcb, out, nullptr, BT_, V_, D_);

    // loss
    loss_partial_kernel<<<BT_, 256>>>(out, y);
    long long logits_elems = (long long)BT_ * V_;
    if ((long long)out_size > logits_elems) {
        loss_mean_kernel<<<1, 256>>>(out + (size_t)logits_elems);
    }
}

// round 16
// speedup vs baseline: 1.4573x; 1.2273x over previous
#include <cuda_runtime.h>
#include <cuda_fp16.h>
#include <cstdint>
#include <math.h>

#define B_  4
#define T_  1024
#define E_  1024
#define H_  16
#define HS_ 64
#define D_  1024
#define V_  32000
#define BT_ 4096
#define QKV3 (3*D_)
#define PN_  (V_/32)        // LSE partials per row

// ---------------- scratch (device globals; no allocation allowed) ----------
__device__ __half g_hh[BT_*E_];                         // embed fp16
__device__ __half g_qkvh[(size_t)BT_*QKV3];             // q|k|v fp16
__device__ __half g_oh[BT_*D_];                         // attn out fp16
__device__ __half g_fh[BT_*D_];                         // ff out fp16
__device__ __half g_wqkvh[(size_t)E_*QKV3];             // [k][n]
__device__ __half g_wfh[(size_t)D_*D_];                 // [k][n]
__device__ __half g_wch[(size_t)D_*V_];                 // [k][n]
__device__ float  g_pm[(size_t)BT_*PN_], g_ps[(size_t)BT_*PN_];
__device__ float  g_loss[BT_];

// ---------------- FFMA-only exp (low-register contexts) ---------------------
__device__ __forceinline__ float fast_exp(float x) {
    float y = fmaxf(x * 1.44269504f, -126.0f);
    float r = y + 12582912.0f;
    int   n = __float_as_int(r) - 0x4B400000;
    float f = y - (r - 12582912.0f);
    float p =             1.33335581e-3f;
    p = fmaf(p, f, 9.61812911e-3f);
    p = fmaf(p, f, 5.55041087e-2f);
    p = fmaf(p, f, 2.40226507e-1f);
    p = fmaf(p, f, 6.93147181e-1f);
    p = fmaf(p, f, 1.0f);
    return p * __int_as_float((n + 127) << 23);
}

__device__ __forceinline__ uint32_t h2u(__half2 h) { return *(uint32_t*)&h; }

// ---------------- embedding: h = tok_emb[x] + pos_emb[t] -> fp16 ------------
__global__ __launch_bounds__(256) void embed_split(const int* __restrict__ x,
                                                   const float* __restrict__ tok,
                                                   const float* __restrict__ pos) {
    int idx = blockIdx.x * 256 + threadIdx.x;
    int r = idx >> 8;
    int c = idx & 255;
    int token = x[r];
    int t = r & (T_ - 1);
    float4 a = ((const float4*)tok)[(size_t)token * 256 + c];
    float4 b = ((const float4*)pos)[(size_t)t * 256 + c];
    ((__half2*)g_hh)[idx * 2 + 0] = __halves2half2(
        __float2half(a.x + b.x), __float2half(a.y + b.y));
    ((__half2*)g_hh)[idx * 2 + 1] = __halves2half2(
        __float2half(a.z + b.z), __float2half(a.w + b.w));
}

// ---------------- elementwise fp32 -> fp16 convert ---------------------------
__global__ __launch_bounds__(256) void wconv(const float* __restrict__ W,
                                             __half* __restrict__ hi) {
    size_t i = ((size_t)blockIdx.x * 256 + threadIdx.x) * 4;
    float4 v = *(const float4*)(W + i);
    ((__half2*)(hi + i))[0] = __halves2half2(__float2half(v.x), __float2half(v.y));
    ((__half2*)(hi + i))[1] = __halves2half2(__float2half(v.z), __float2half(v.w));
}

// QKV gather convert: W[H][E][HS] fp32 -> out[k][h*64+hs] fp16 (stride QKV3)
__global__ __launch_bounds__(256) void wconv_qkv(const float* __restrict__ W,
                                                 __half* __restrict__ out) {
    int idx = blockIdx.x * 256 + threadIdx.x;
    int i = idx << 2;
    int h  = i >> 16;
    int k  = (i >> 6) & 1023;
    int hs = i & 63;
    float4 v = ((const float4*)W)[idx];
    size_t o = (size_t)k * QKV3 + h * 64 + hs;
    ((__half2*)(out + o))[0] = __halves2half2(__float2half(v.x), __float2half(v.y));
    ((__half2*)(out + o))[1] = __halves2half2(__float2half(v.z), __float2half(v.w));
}

// ---------------- fp16 tensor-core GEMM (B in [K][N] layout) ----------------
// OUTMODE: 0 = fp32 C, 2 = half C
#define SSTR  40
#define ATILE (128*SSTR)
#define SSTRB 136
#define BTILE (32*SSTRB)

__device__ __forceinline__ void cpa16(uint32_t dst, const void* src) {
    asm volatile("cp.async.cg.shared.global [%0], [%1], 16;\n" :: "r"(dst), "l"(src));
}
#define LDM4(R, ADDR) \
    asm volatile("ldmatrix.sync.aligned.m8n8.x4.shared.b16 {%0,%1,%2,%3}, [%4];" \
        : "=r"(R[0]), "=r"(R[1]), "=r"(R[2]), "=r"(R[3]) : "r"(ADDR))
#define LDM4T(R, ADDR) \
    asm volatile("ldmatrix.sync.aligned.m8n8.x4.trans.shared.b16 {%0,%1,%2,%3}, [%4];" \
        : "=r"(R[0]), "=r"(R[1]), "=r"(R[2]), "=r"(R[3]) : "r"(ADDR))
#define MMAF16(Cc, Aa, B0, B1) \
    asm volatile("mma.sync.aligned.m16n8k16.row.col.f32.f16.f16.f32 " \
        "{%0,%1,%2,%3}, {%4,%5,%6,%7}, {%8,%9}, {%0,%1,%2,%3};" \
        : "+f"(Cc[0]), "+f"(Cc[1]), "+f"(Cc[2]), "+f"(Cc[3]) \
        : "r"(Aa[0]), "r"(Aa[1]), "r"(Aa[2]), "r"(Aa[3]), "r"(B0), "r"(B1))

template <int HASBIAS, int RELU, int OUTMODE, int LSE>
__global__ __launch_bounds__(256) void mma_gemm(
    const __half* __restrict__ Ah,
    const __half* __restrict__ Bh,
    const float* __restrict__ bias, float* __restrict__ C,
    __half* __restrict__ Ch,
    int M, int N, int K)
{
    extern __shared__ __half sm[];
    constexpr int STG = ATILE + BTILE;
    const int m0 = blockIdx.x * 128, n0 = blockIdx.y * 128;
    const int tid = threadIdx.x;
    const int lane = tid & 31, w = tid >> 5;
    const int wm = w >> 2, wn = w & 3;
    const uint32_t smb = (uint32_t)__cvta_generic_to_shared(sm);

    const int nk = K >> 5;

    auto load_stage = [&](int s, int k0g) {
#pragma unroll
        for (int hlf = 0; hlf < 2; hlf++) {
            int rem = (hlf << 8) + tid;
            int row = rem >> 2, seg = tid & 3;
            const __half* src = Ah + (size_t)(m0 + row) * K + k0g + seg * 8;
            uint32_t dst = smb + (uint32_t)((s * STG + row * SSTR + seg * 8) << 1);
            cpa16(dst, src);
        }
#pragma unroll
        for (int it = 0; it < 2; it++) {
            int idx = it * 256 + tid;
            int row = idx >> 4, seg = idx & 15;
            const __half* src = Bh + (size_t)(k0g + row) * N + n0 + seg * 8;
            uint32_t dst = smb + (uint32_t)((s * STG + ATILE + row * SSTRB + seg * 8) << 1);
            cpa16(dst, src);
        }
        asm volatile("cp.async.commit_group;\n" ::: "memory");
    };

    load_stage(0, 0);
    load_stage(1, 32);

    float acc[4][4][4];
#pragma unroll
    for (int a = 0; a < 4; a++)
#pragma unroll
        for (int b = 0; b < 4; b++)
#pragma unroll
            for (int c = 0; c < 4; c++) acc[a][b][c] = 0.f;

    const int t8 = lane >> 3, r8 = lane & 7;
    const int g2 = lane >> 3;

    for (int kt = 0; kt < nk; kt++) {
        asm volatile("cp.async.wait_group 1;\n" ::: "memory");
        __syncthreads();
        const uint32_t base = smb + (uint32_t)(((kt & 1) * STG) << 1);
#pragma unroll
        for (int kk = 0; kk < 2; kk++) {
            const int kof = kk << 4;
            uint32_t ah[4][4], bh[2][4];
#pragma unroll
            for (int mt = 0; mt < 4; mt++) {
                int mrow = wm * 64 + mt * 16 + ((t8 & 1) << 3) + r8;
                int kcol = kof + ((t8 >> 1) << 3);
                uint32_t ad = base + (uint32_t)((mrow * SSTR + kcol) << 1);
                LDM4(ah[mt], ad);
            }
#pragma unroll
            for (int np = 0; np < 2; np++) {
                int krow = kof + ((g2 & 1) << 3) + (lane & 7);
                int ncol = wn * 32 + np * 16 + ((g2 >> 1) << 3);
                uint32_t bd = base + (uint32_t)((ATILE + krow * SSTRB + ncol) << 1);
                LDM4T(bh[np], bd);
            }
#pragma unroll
            for (int mt = 0; mt < 4; mt++)
#pragma unroll
                for (int np = 0; np < 2; np++)
#pragma unroll
                    for (int hf = 0; hf < 2; hf++) {
                        float* cc = acc[mt][np * 2 + hf];
                        MMAF16(cc, ah[mt], bh[np][hf * 2], bh[np][hf * 2 + 1]);
                    }
        }
        __syncthreads();
        if (kt + 2 < nk) load_stage(kt & 1, (kt + 2) << 5);
        else asm volatile("cp.async.commit_group;\n" ::: "memory");
    }

    // ---------------- epilogue ----------------
    float bj[8];
#pragma unroll
    for (int nt = 0; nt < 4; nt++) {
        int col = n0 + wn * 32 + nt * 8 + ((lane & 3) << 1);
        bj[nt * 2 + 0] = HASBIAS ? bias[col] : 0.f;
        bj[nt * 2 + 1] = HASBIAS ? bias[col + 1] : 0.f;
    }
#pragma unroll
    for (int mt = 0; mt < 4; mt++) {
#pragma unroll
        for (int hf = 0; hf < 2; hf++) {
            int row = m0 + wm * 64 + mt * 16 + (lane >> 2) + hf * 8;
            float vv[8];
            float vmax = -INFINITY;
#pragma unroll
            for (int nt = 0; nt < 4; nt++) {
#pragma unroll
                for (int j = 0; j < 2; j++) {
                    float v = acc[mt][nt][hf * 2 + j] + bj[nt * 2 + j];
                    if (RELU) v = fmaxf(v, 0.f);
                    vv[nt * 2 + j] = v;
                    vmax = fmaxf(vmax, v);
                }
            }
#pragma unroll
            for (int nt = 0; nt < 4; nt++) {
                int col = n0 + wn * 32 + nt * 8 + ((lane & 3) << 1);
                if (OUTMODE == 2) {
                    *(__half2*)(Ch + (size_t)row * N + col) = __halves2half2(
                        __float2half(vv[nt * 2]), __float2half(vv[nt * 2 + 1]));
                } else {
                    float2 o; o.x = vv[nt * 2]; o.y = vv[nt * 2 + 1];
                    *(float2*)(C + (size_t)row * N + col) = o;
                }
            }
            if (LSE) {
                float rs = 0.f;
#pragma unroll
                for (int k = 0; k < 8; k++) rs += fast_exp(vv[k] - vmax);
                float rm = vmax;
#pragma unroll
                for (int off = 1; off <= 2; off <<= 1) {
                    float m2 = __shfl_xor_sync(0xFFFFFFFFu, rm, off);
                    float s2 = __shfl_xor_sync(0xFFFFFFFFu, rs, off);
                    float mn = fmaxf(rm, m2);
                    rs = rs * fast_exp(rm - mn) + s2 * fast_exp(m2 - mn);
                    rm = mn;
                }
                if ((lane & 3) == 0) {
                    int pcol = blockIdx.y * 4 + wn;
                    g_pm[(size_t)row * PN_ + pcol] = rm;
                    g_ps[(size_t)row * PN_ + pcol] = rs;
                }
            }
        }
    }
}

// ---------------- tensor-core causal flash attention -------------------------
// block = (b,h) x paired 64-query tiles (15-px, px); 128 threads = 4 warps;
// warp w owns query rows [w*16, w*16+16) of the tile.
#define AS 72    // half elems per smem row (64 + 8 pad; 144 B = 16B-aligned)

__global__ __launch_bounds__(128) void attn_mma() {
    __shared__ __half sq[64 * AS], sk[64 * AS], sv[64 * AS];
    const int z   = blockIdx.y;
    const int b   = z >> 4;
    const int hh  = z & 15;
    const int px  = blockIdx.x;            // 0..7
    const int tid = threadIdx.x;
    const int lane = tid & 31, w = tid >> 5;
    const int t8 = lane >> 3, r8 = lane & 7;
    const uint32_t sqb = (uint32_t)__cvta_generic_to_shared(sq);
    const uint32_t skb = (uint32_t)__cvta_generic_to_shared(sk);
    const uint32_t svb = (uint32_t)__cvta_generic_to_shared(sv);

    const float qscale = 8.0f;             // sqrt(HS)

#pragma unroll
    for (int half = 0; half < 2; half++) {
        const int qt = (half == 0) ? (15 - px) : px;

        // ---- load Q tile (64 x 64 fp16) ----
#pragma unroll
        for (int i = 0; i < 4; i++) {
            int idx = tid + i * 128;
            int r = idx >> 3, seg = idx & 7;
            const __half* src = g_qkvh + (size_t)(b * T_ + qt * 64 + r) * QKV3
                              + hh * 64 + seg * 8;
            cpa16(sqb + (uint32_t)((r * AS + seg * 8) << 1), src);
        }
        asm volatile("cp.async.commit_group;\n" ::: "memory");
        asm volatile("cp.async.wait_group 0;\n" ::: "memory");
        __syncthreads();

        // ---- Q A-fragments (4 k-steps) ----
        uint32_t qa[4][4];
#pragma unroll
        for (int kt = 0; kt < 4; kt++) {
            int mrow = w * 16 + ((t8 & 1) << 3) + r8;
            int kcol = kt * 16 + ((t8 >> 1) << 3);
            LDM4(qa[kt], sqb + (uint32_t)((mrow * AS + kcol) << 1));
        }
        __syncthreads();   // sq free (qa in regs); not reused until next half

        float m0 = -INFINITY, m1 = -INFINITY, l0 = 0.f, l1 = 0.f;
        float oacc[8][4];
#pragma unroll
        for (int a = 0; a < 8; a++)
#pragma unroll
            for (int c = 0; c < 4; c++) oacc[a][c] = 0.f;

        const int row0 = qt * 64 + w * 16 + (lane >> 2);
        const int row1 = row0 + 8;
        const int nch = qt + 1;

        for (int ch = 0; ch < nch; ch++) {
            const int s0 = ch * 64;
            // ---- load K,V chunk (64 x 64 fp16 each) ----
#pragma unroll
            for (int i = 0; i < 4; i++) {
                int idx = tid + i * 128;
                int r = idx >> 3, seg = idx & 7;
                size_t gbase = (size_t)(b * T_ + s0 + r) * QKV3 + hh * 64 + seg * 8;
                cpa16(skb + (uint32_t)((r * AS + seg * 8) << 1), g_qkvh + gbase + D_);
                cpa16(svb + (uint32_t)((r * AS + seg * 8) << 1), g_qkvh + gbase + 2 * D_);
            }
            asm volatile("cp.async.commit_group;\n" ::: "memory");
            asm volatile("cp.async.wait_group 0;\n" ::: "memory");
            __syncthreads();

            // ---- S = Q @ K^T  (8 key n-tiles x 4 accum) ----
            float sacc[8][4];
#pragma unroll
            for (int a = 0; a < 8; a++)
#pragma unroll
                for (int c = 0; c < 4; c++) sacc[a][c] = 0.f;
#pragma unroll
            for (int kt = 0; kt < 4; kt++) {
#pragma unroll
                for (int np = 0; np < 4; np++) {
                    int nrow = np * 16 + ((t8 >> 1) << 3) + r8;
                    int kcol = kt * 16 + ((t8 & 1) << 3);
                    uint32_t kb[4];
                    LDM4(kb, skb + (uint32_t)((nrow * AS + kcol) << 1));
                    MMAF16(sacc[np * 2 + 0], qa[kt], kb[0], kb[1]);
                    MMAF16(sacc[np * 2 + 1], qa[kt], kb[2], kb[3]);
                }
            }

            // ---- causal mask (diagonal chunk only) + scale ----
#pragma unroll
            for (int nt = 0; nt < 8; nt++) {
#pragma unroll
                for (int j = 0; j < 2; j++) {
                    int col = s0 + nt * 8 + ((lane & 3) << 1) + j;
                    sacc[nt][j]     = (ch == qt && col > row0) ? -1e30f
                                      : sacc[nt][j] * qscale;
                    sacc[nt][j + 2] = (ch == qt && col > row1) ? -1e30f
                                      : sacc[nt][j + 2] * qscale;
                }
            }

            // ---- row max (local then quad shfl) ----
            float r0m = -INFINITY, r1m = -INFINITY;
#pragma unroll
            for (int nt = 0; nt < 8; nt++) {
                r0m = fmaxf(r0m, fmaxf(sacc[nt][0], sacc[nt][1]));
                r1m = fmaxf(r1m, fmaxf(sacc[nt][2], sacc[nt][3]));
            }
#pragma unroll
            for (int off = 1; off <= 2; off <<= 1) {
                r0m = fmaxf(r0m, __shfl_xor_sync(0xFFFFFFFFu, r0m, off));
                r1m = fmaxf(r1m, __shfl_xor_sync(0xFFFFFFFFu, r1m, off));
            }
            float mn0 = fmaxf(m0, r0m), mn1 = fmaxf(m1, r1m);
            float sc0 = __expf(m0 - mn0), sc1 = __expf(m1 - mn1);
            l0 *= sc0; l1 *= sc1;
#pragma unroll
            for (int nt = 0; nt < 8; nt++) {
                oacc[nt][0] *= sc0; oacc[nt][1] *= sc0;
                oacc[nt][2] *= sc1; oacc[nt][3] *= sc1;
            }
            m0 = mn0; m1 = mn1;

            // ---- p = exp(s - m), accumulate partial l, pack to fp16 ----
#pragma unroll
            for (int nt = 0; nt < 8; nt++) {
                float p0 = __expf(sacc[nt][0] - mn0);
                float p1 = __expf(sacc[nt][1] - mn0);
                float p2 = __expf(sacc[nt][2] - mn1);
                float p3 = __expf(sacc[nt][3] - mn1);
                l0 += p0 + p1; l1 += p2 + p3;
                sacc[nt][0] = p0; sacc[nt][1] = p1;
                sacc[nt][2] = p2; sacc[nt][3] = p3;
            }

            // ---- O += P @ V ----
#pragma unroll
            for (int kt = 0; kt < 4; kt++) {
                uint32_t pa[4];
                pa[0] = h2u(__floats2half2_rn(sacc[2*kt][0],   sacc[2*kt][1]));
                pa[1] = h2u(__floats2half2_rn(sacc[2*kt][2],   sacc[2*kt][3]));
                pa[2] = h2u(__floats2half2_rn(sacc[2*kt+1][0], sacc[2*kt+1][1]));
                pa[3] = h2u(__floats2half2_rn(sacc[2*kt+1][2], sacc[2*kt+1][3]));
#pragma unroll
                for (int nd = 0; nd < 4; nd++) {
                    int krow = kt * 16 + ((t8 & 1) << 3) + (lane & 7);
                    int ncol = nd * 16 + ((t8 >> 1) << 3);
                    uint32_t vb[4];
                    LDM4T(vb, svb + (uint32_t)((krow * AS + ncol) << 1));
                    MMAF16(oacc[nd * 2 + 0], pa, vb[0], vb[1]);
                    MMAF16(oacc[nd * 2 + 1], pa, vb[2], vb[3]);
                }
            }
            __syncthreads();   // before next chunk overwrites sk/sv
        }

        // ---- finalize: quad-sum l, normalize, store fp16 ----
#pragma unroll
        for (int off = 1; off <= 2; off <<= 1) {
            l0 += __shfl_xor_sync(0xFFFFFFFFu, l0, off);
            l1 += __shfl_xor_sync(0xFFFFFFFFu, l1, off);
        }
        float inv0 = 1.f / l0, inv1 = 1.f / l1;
#pragma unroll
        for (int nt = 0; nt < 8; nt++) {
            int col = hh * 64 + nt * 8 + ((lane & 3) << 1);
            *(__half2*)(g_oh + (size_t)(b * T_ + row0) * D_ + col) =
                __halves2half2(__float2half(oacc[nt][0] * inv0),
                               __float2half(oacc[nt][1] * inv0));
            *(__half2*)(g_oh + (size_t)(b * T_ + row1) * D_ + col) =
                __halves2half2(__float2half(oacc[nt][2] * inv1),
                               __float2half(oacc[nt][3] * inv1));
        }
        __syncthreads();   // before next half reuses sq
    }
}

// ---------------- loss from LSE partials -------------------------------------
__global__ __launch_bounds__(256) void loss_partial_kernel(const float* __restrict__ logits,
                                                           const int* __restrict__ y) {
    __shared__ float sm_m[256], sm_s[256];
    int row = blockIdx.x;
    int tid = threadIdx.x;
    float m = -INFINITY, s = 0.f;
    for (int i = tid; i < PN_; i += 256) {
        float m2 = g_pm[(size_t)row * PN_ + i];
        float s2 = g_ps[(size_t)row * PN_ + i];
        float mn = fmaxf(m, m2);
        s = s * fast_exp(m - mn) + s2 * fast_exp(m2 - mn);
        m = mn;
    }
    sm_m[tid] = m; sm_s[tid] = s;
    __syncthreads();
    for (int k = 128; k > 0; k >>= 1) {
        if (tid < k) {
            float m2 = sm_m[tid + k], s2 = sm_s[tid + k];
            float mn = fmaxf(sm_m[tid], m2);
            sm_s[tid] = sm_s[tid] * fast_exp(sm_m[tid] - mn) + s2 * fast_exp(m2 - mn);
            sm_m[tid] = mn;
        }
        __syncthreads();
    }
    if (tid == 0) {
        g_loss[row] = sm_m[0] + logf(sm_s[0]) - logits[(size_t)row * V_ + y[row]];
    }
}

__global__ __launch_bounds__(256) void loss_mean_kernel(float* out) {
    __shared__ float red[256];
    int tid = threadIdx.x;
    float s = 0.f;
    for (int i = tid; i < BT_; i += 256) s += g_loss[i];
    red[tid] = s;
    __syncthreads();
    for (int k = 128; k > 0; k >>= 1) {
        if (tid < k) red[tid] += red[tid + k];
        __syncthreads();
    }
    if (tid == 0) *out = red[0] / (float)BT_;
}

// ---------------- launch ----------------------------------------------------
extern "C" void kernel_launch(void* const* d_in, const int* in_sizes, int n_in,
                              void* d_out, int out_size) {
    const int*   x   = (const int*)d_in[0];
    const int*   y   = (const int*)d_in[1];
    const float* tok = (const float*)d_in[2];
    const float* pos = (const float*)d_in[3];
    const float* Wq  = (const float*)d_in[4];
    const float* Wk  = (const float*)d_in[5];
    const float* Wv  = (const float*)d_in[6];
    const float* ffw = (const float*)d_in[7];
    const float* ffb = (const float*)d_in[8];
    const float* fcw = (const float*)d_in[9];
    const float* fcb = (const float*)d_in[10];
    float* out = (float*)d_out;

    __half *phh, *pqkvh, *poh, *pfh, *pwqh, *pwfh, *pwch;
    cudaGetSymbolAddress((void**)&phh, g_hh);
    cudaGetSymbolAddress((void**)&pqkvh, g_qkvh);
    cudaGetSymbolAddress((void**)&poh, g_oh);
    cudaGetSymbolAddress((void**)&pfh, g_fh);
    cudaGetSymbolAddress((void**)&pwqh, g_wqkvh);
    cudaGetSymbolAddress((void**)&pwfh, g_wfh);
    cudaGetSymbolAddress((void**)&pwch, g_wch);

    const int smem1 = 2 * (ATILE + BTILE) * 2;   // 37888 B
    cudaFuncSetAttribute(mma_gemm<0,0,2,0>, cudaFuncAttributeMaxDynamicSharedMemorySize, smem1);
    cudaFuncSetAttribute(mma_gemm<1,1,2,0>, cudaFuncAttributeMaxDynamicSharedMemorySize, smem1);
    cudaFuncSetAttribute(mma_gemm<1,0,0,1>, cudaFuncAttributeMaxDynamicSharedMemorySize, smem1);

    // embedding
    embed_split<<<(BT_ * E_ / 4) / 256, 256>>>(x, tok, pos);

    // weight converts (elementwise, no transpose)
    wconv_qkv<<<(H_*E_*HS_/4)/256, 256>>>(Wq, pwqh);
    wconv_qkv<<<(H_*E_*HS_/4)/256, 256>>>(Wk, pwqh + D_);
    wconv_qkv<<<(H_*E_*HS_/4)/256, 256>>>(Wv, pwqh + 2*D_);
    wconv<<<(D_*D_/4)/256, 256>>>(ffw, pwfh);
    wconv<<<((size_t)D_*V_/4)/256, 256>>>(fcw, pwch);

    // fused QKV GEMM -> fp16 q|k|v
    mma_gemm<0,0,2,0><<<dim3(BT_/128, QKV3/128), 256, smem1>>>(
        phh, pwqh, nullptr, nullptr, pqkvh, BT_, QKV3, E_);

    // tensor-core flash attention (work-balanced tile pairs)
    attn_mma<<<dim3(8, B_*H_), 128>>>();

    // FF: relu(o @ ff_w + ff_b) -> fp16
    mma_gemm<1,1,2,0><<<dim3(BT_/128, D_/128), 256, smem1>>>(
        poh, pwfh, ffb, nullptr, pfh, BT_, D_, D_);

    // logits: ff @ fc_w + fc_b -> d_out fp32 (fused LSE partials)
    mma_gemm<1,0,0,1><<<dim3(BT_/128, V_/128), 256, smem1>>>(
        pfh, pwch, fcb, out, nullptr, BT_, V_, D_);

    // loss
    loss_partial_kernel<<<BT_, 256>>>(out, y);
    long long logits_elems = (long long)BT_ * V_;
    if ((long long)out_size > logits_elems) {
        loss_mean_kernel<<<1, 256>>>(out + (size_t)logits_elems);
    }
}